// round 2
// baseline (speedup 1.0000x reference)
#include <cuda_runtime.h>
#include <cuda_bf16.h>
#include <stdint.h>

#define N 8192
#define NCHUNK 128            // N/64
#define IOU_THR 0.5f

// ---------------- device scratch (no allocations allowed) ----------------
__device__ float4 g_boxes[N];                 // decoded boxes, original order
__device__ float  g_ctr[N];                   // centerness, original order
__device__ int    g_maxbits;                  // boxes.max() as float bits (max is positive)
__device__ int    g_order[N];                 // sorted position -> original index
__device__ float4 g_sboxes[N];                // sorted, class-offset boxes
__device__ float  g_sarea[N];                 // areas of sorted offset boxes
__device__ unsigned long long g_mask[(size_t)N * NCHUNK];  // TRANSPOSED: [cb*N + row]
__device__ unsigned long long g_keptw[NCHUNK];             // published kept word per chunk
__device__ int    g_flag[NCHUNK];                           // publish flags
__device__ unsigned char g_keep[N];           // keep flag, original order

// ---------------- K0: reset accumulators/flags each replay ----------------
__global__ __launch_bounds__(128) void init_kernel() {
    int t = threadIdx.x;
    if (t == 0) g_maxbits = 0;   // +0.0f; true max >= 36 so signed-int atomicMax works
    g_flag[t] = 0;
}

// ---------------- K1: decode boxes, centerness, global max ----------------
__global__ __launch_bounds__(256) void decode_kernel(const float* __restrict__ deltas,
                                                     const float* __restrict__ loc,
                                                     const float* __restrict__ gt,
                                                     const int*   __restrict__ stride_p) {
    int i = blockIdx.x * 256 + threadIdx.x;
    if (i >= N) return;
    float s  = (float)stride_p[0];
    float xc = loc[2 * i + 0];
    float yc = loc[2 * i + 1];
    float d0 = fmaxf(deltas[4 * i + 0], 0.0f);
    float d1 = fmaxf(deltas[4 * i + 1], 0.0f);
    float d2 = fmaxf(deltas[4 * i + 2], 0.0f);
    float d3 = fmaxf(deltas[4 * i + 3], 0.0f);
    float x1 = __fsub_rn(xc, __fmul_rn(d0, s));
    float y1 = __fsub_rn(yc, __fmul_rn(d1, s));
    float x2 = __fadd_rn(xc, __fmul_rn(d2, s));
    float y2 = __fadd_rn(yc, __fmul_rn(d3, s));
    g_boxes[i] = make_float4(x1, y1, x2, y2);

    float l = __fdiv_rn(__fsub_rn(xc, gt[4 * i + 0]), s);
    float t = __fdiv_rn(__fsub_rn(yc, gt[4 * i + 1]), s);
    float r = __fdiv_rn(__fsub_rn(gt[4 * i + 2], xc), s);
    float b = __fdiv_rn(__fsub_rn(gt[4 * i + 3], yc), s);
    float num = __fmul_rn(fminf(l, r), fminf(t, b));
    float den = __fmul_rn(fmaxf(l, r), fmaxf(t, b));
    g_ctr[i] = __fsqrt_rn(__fdiv_rn(num, den));

    float m = fmaxf(fmaxf(x1, y1), fmaxf(x2, y2));
    #pragma unroll
    for (int o = 16; o > 0; o >>= 1)
        m = fmaxf(m, __shfl_xor_sync(0xFFFFFFFFu, m, o));
    if ((threadIdx.x & 31) == 0)
        atomicMax(&g_maxbits, __float_as_int(m));
}

// ---------------- K2: stable sort by (-score, idx) ----------------
__global__ __launch_bounds__(1024) void sort_kernel(const float* __restrict__ scores) {
    extern __shared__ unsigned long long sk[];
    int t = threadIdx.x;
    for (int p = t; p < N; p += 1024) {
        unsigned sb = __float_as_uint(scores[p]);   // scores >= 0 -> bits monotonic
        sk[p] = ((unsigned long long)(sb ^ 0xFFFFFFFFu) << 32) | (unsigned)p;
    }
    __syncthreads();
    for (int k = 2; k <= N; k <<= 1) {
        for (int j = k >> 1; j > 0; j >>= 1) {
            for (int p = t; p < N; p += 1024) {
                int q = p ^ j;
                if (q > p) {
                    bool up = ((p & k) == 0);
                    unsigned long long a = sk[p], b = sk[q];
                    if ((a > b) == up) { sk[p] = b; sk[q] = a; }
                }
            }
            __syncthreads();
        }
    }
    for (int p = t; p < N; p += 1024)
        g_order[p] = (int)(sk[p] & 0xFFFFFFFFu);
}

// ---------------- K3: gather sorted class-offset boxes + areas ----------------
__global__ __launch_bounds__(256) void gather_kernel(const int* __restrict__ class_ids) {
    int p = blockIdx.x * 256 + threadIdx.x;
    if (p >= N) return;
    int o = g_order[p];
    float maxv  = __int_as_float(g_maxbits);
    float scale = __fadd_rn(maxv, 1.0f);
    float off   = __fmul_rn((float)class_ids[o], scale);
    float4 b = g_boxes[o];
    float4 bn;
    bn.x = __fadd_rn(b.x, off);
    bn.y = __fadd_rn(b.y, off);
    bn.z = __fadd_rn(b.z, off);
    bn.w = __fadd_rn(b.w, off);
    g_sboxes[p] = bn;
    g_sarea[p]  = __fmul_rn(__fsub_rn(bn.z, bn.x), __fsub_rn(bn.w, bn.y));
}

// ---------------- K4: IoU suppression bitmask, warp-per-row + ballot ----------------
// grid = (128 column-chunks, 32 row-groups), 256 threads = 8 warps.
// Warp w: rows rowBase + w*32 .. +31 against columns cb*64 .. cb*64+63.
// Lane l holds columns cb*64+l and cb*64+32+l in registers; row box broadcast by shfl.
// Word (row i, chunk cb) written to g_mask[cb*N + i] (coalesced).
__global__ __launch_bounds__(256) void mask_kernel() {
    int cb      = blockIdx.x;
    int rowBase = blockIdx.y * 256;
    int cbLimit = cb * 64 + 63;
    if (rowBase > cbLimit) return;               // tile fully below diagonal
    int w = threadIdx.x >> 5, l = threadIdx.x & 31;
    int rowStart = rowBase + w * 32;
    if (rowStart > cbLimit) return;              // warp-uniform

    int j1 = cb * 64 + l, j2 = j1 + 32;
    float4 o1 = g_sboxes[j1]; float a1 = g_sarea[j1];
    float4 o2 = g_sboxes[j2]; float a2 = g_sarea[j2];
    float4 rb = g_sboxes[rowStart + l];
    float  ra = g_sarea[rowStart + l];

    unsigned long long myword = 0ull;
    #pragma unroll 4
    for (int r = 0; r < 32; ++r) {
        int i = rowStart + r;
        if (i > cbLimit) break;                  // warp-uniform
        float bx = __shfl_sync(0xFFFFFFFFu, rb.x, r);
        float by = __shfl_sync(0xFFFFFFFFu, rb.y, r);
        float bz = __shfl_sync(0xFFFFFFFFu, rb.z, r);
        float bw = __shfl_sync(0xFFFFFFFFu, rb.w, r);
        float ba = __shfl_sync(0xFFFFFFFFu, ra,   r);

        float iw1 = fmaxf(__fsub_rn(fminf(bz, o1.z), fmaxf(bx, o1.x)), 0.0f);
        float ih1 = fmaxf(__fsub_rn(fminf(bw, o1.w), fmaxf(by, o1.y)), 0.0f);
        float in1 = __fmul_rn(iw1, ih1);
        float dn1 = __fsub_rn(__fadd_rn(ba, a1), in1);
        bool  s1  = (__fdiv_rn(in1, dn1) > IOU_THR) && (j1 > i);   // NaN>thr == false

        float iw2 = fmaxf(__fsub_rn(fminf(bz, o2.z), fmaxf(bx, o2.x)), 0.0f);
        float ih2 = fmaxf(__fsub_rn(fminf(bw, o2.w), fmaxf(by, o2.y)), 0.0f);
        float in2 = __fmul_rn(iw2, ih2);
        float dn2 = __fsub_rn(__fadd_rn(ba, a2), in2);
        bool  s2  = (__fdiv_rn(in2, dn2) > IOU_THR) && (j2 > i);

        unsigned b1 = __ballot_sync(0xFFFFFFFFu, s1);
        unsigned b2 = __ballot_sync(0xFFFFFFFFu, s2);
        if (l == r) myword = (unsigned long long)b1 | ((unsigned long long)b2 << 32);
    }
    int i_l = rowStart + l;
    if (i_l <= cbLimit)
        g_mask[(size_t)cb * N + i_l] = myword;
}

// ---------------- K5: multi-block pipelined greedy NMS reduce ----------------
// 128 blocks (all co-resident, 128 < 148 SMs), 64 threads. Block t owns mask
// column word t. For each earlier chunk c it prefetches its column word for
// rows c*64+k (address kept-independent), waits for kept_c to be published,
// and masked-ORs. At c == t it OR-reduces across threads, serially resolves
// the intra-chunk greedy suppression, publishes kept_t, writes keep flags.
__global__ __launch_bounds__(64, 1) void reduce_kernel() {
    int t = blockIdx.x;
    int k = threadIdx.x;
    __shared__ unsigned long long s_kept;
    __shared__ unsigned long long s_red[64];
    __shared__ unsigned long long s_diag[64];
    const unsigned long long* col = g_mask + (size_t)t * N;

    unsigned long long acc = 0ull;
    for (int c = 0; c < t; ++c) {
        unsigned long long w = col[c * 64 + k];          // issued before the wait
        if (k == 0) {
            while (((volatile int*)g_flag)[c] == 0) { }
            __threadfence();
            s_kept = g_keptw[c];
        }
        __syncthreads();
        unsigned long long kk = s_kept;
        __syncthreads();
        acc |= w & (0ull - ((kk >> k) & 1ull));          // branchless masked OR
    }

    s_red[k]  = acc;
    s_diag[k] = col[t * 64 + k];                         // diag word: only bits > k set
    __syncthreads();
    #pragma unroll
    for (int off = 32; off >= 1; off >>= 1) {
        if (k < off) s_red[k] |= s_red[k + off];
        __syncthreads();
    }

    if (k == 0) {
        unsigned long long rem  = s_red[0];
        unsigned long long kept = 0ull;
        unsigned long long cand = ~rem;
        while (cand) {
            int b = __ffsll(cand) - 1;
            kept |= 1ull << b;
            rem  |= s_diag[b];
            cand &= ~(rem | (1ull << b));
        }
        g_keptw[t] = kept;
        __threadfence();
        atomicExch(&g_flag[t], 1);
        s_kept = kept;
    }
    __syncthreads();

    unsigned long long kw = s_kept;
    int o = g_order[t * 64 + k];
    g_keep[o] = (unsigned char)((kw >> k) & 1ull);
}

// ---------------- K6: assemble output ----------------
__global__ __launch_bounds__(256) void output_kernel(float* __restrict__ out) {
    int i = blockIdx.x * 256 + threadIdx.x;
    if (i >= N) return;
    float kf = (float)g_keep[i];
    float4 b = g_boxes[i];
    out[6 * i + 0] = __fmul_rn(b.x, kf);
    out[6 * i + 1] = __fmul_rn(b.y, kf);
    out[6 * i + 2] = __fmul_rn(b.z, kf);
    out[6 * i + 3] = __fmul_rn(b.w, kf);
    out[6 * i + 4] = g_ctr[i];
    out[6 * i + 5] = kf;
}

// ---------------- launch ----------------
extern "C" void kernel_launch(void* const* d_in, const int* in_sizes, int n_in,
                              void* d_out, int out_size) {
    const float* deltas = (const float*)d_in[0];
    const float* loc    = (const float*)d_in[1];
    const float* scores = (const float*)d_in[2];
    const int*   cls    = (const int*)  d_in[3];
    const float* gt     = (const float*)d_in[4];
    const int*   stride = (const int*)  d_in[5];
    float* out = (float*)d_out;

    cudaFuncSetAttribute(sort_kernel, cudaFuncAttributeMaxDynamicSharedMemorySize, N * 8);

    init_kernel<<<1, 128>>>();
    decode_kernel<<<N / 256, 256>>>(deltas, loc, gt, stride);
    sort_kernel<<<1, 1024, N * 8>>>(scores);
    gather_kernel<<<N / 256, 256>>>(cls);
    mask_kernel<<<dim3(NCHUNK, 32), 256>>>();
    reduce_kernel<<<NCHUNK, 64>>>();
    output_kernel<<<N / 256, 256>>>(out);
}